// round 14
// baseline (speedup 1.0000x reference)
#include <cuda_runtime.h>
#include <cuda_bf16.h>
#include <math.h>

// Problem constants (padded)
#define DIM   64
#define NMAX  10016              // 313 blocks * 32 nodes
#define EMAX  40064              // 313 tiles * 128 rows
#define GEMM_SMEM (2 * 64 * 132 * 4)

// ---------------- scratch (device globals; no allocation allowed) ----------
__device__ __align__(128) float g_out[NMAX * DIM];        // h == out
__device__ __align__(128) float g_agg[NMAX * DIM];
__device__ __align__(128) float g_deg[NMAX];
__device__ __align__(128) float g_t[EMAX * DIM];          // edge MLP hidden
__device__ __align__(128) float g_we[40064UL * 4096UL];   // edge weights [E,64,64], 656MB
__device__ __align__(128) float g_wihT[64 * 192];
__device__ __align__(128) float g_whhT[64 * 192];
__device__ __align__(128) float g_qstar[128];
__device__ __align__(128) float g_hl[64];
__device__ __align__(128) float g_cl[64];
__device__ __align__(128) float g_q[64];
__device__ __align__(128) float g_r[64];
__device__ __align__(128) float g_e[NMAX];
__device__ float g_sumexp;
__device__ float g_emax;

__device__ __forceinline__ float sigmoidf(float x) { return 1.f / (1.f + expf(-x)); }

__device__ __forceinline__ void atomicMaxF(float* addr, float val) {
    int old = __float_as_int(*addr);
    while (__int_as_float(old) < val) {
        int prev = atomicCAS((int*)addr, old, __float_as_int(val));
        if (prev == old) break;
        old = prev;
    }
}

// ---------------- init: zero deg + set2set state ----------------------------
__global__ void init_kernel() {
    int idx = blockIdx.x * blockDim.x + threadIdx.x;
    if (idx < NMAX) g_deg[idx] = 0.f;
    if (idx < 128) g_qstar[idx] = 0.f;
    if (idx < 64) { g_hl[idx] = 0.f; g_cl[idx] = 0.f; }
}

__global__ void deg_kernel(const int* __restrict__ ei, int e) {
    int idx = blockIdx.x * blockDim.x + threadIdx.x;
    if (idx < e) atomicAdd(&g_deg[ei[e + idx]], 1.f);
}

// out = relu(x @ lin0_w.T + b)
__global__ void lin0_kernel(const float* __restrict__ x, const float* __restrict__ w,
                            const float* __restrict__ b, int n) {
    int idx = blockIdx.x * blockDim.x + threadIdx.x;
    if (idx >= n * DIM) return;
    int node = idx >> 6, o = idx & 63;
    const float* xr = x + node * 3;
    float acc = b[o] + xr[0] * w[o * 3 + 0] + xr[1] * w[o * 3 + 1] + xr[2] * w[o * 3 + 2];
    g_out[idx] = fmaxf(acc, 0.f);
}

// t = relu(edge_attr @ em1_w.T + em1_b)
__global__ void edge_mlp1_kernel(const float* __restrict__ ea, const float* __restrict__ w,
                                 const float* __restrict__ b, int e) {
    int idx = blockIdx.x * blockDim.x + threadIdx.x;
    if (idx >= e * DIM) return;
    int ed = idx >> 6, k = idx & 63;
    const float* er = ea + ed * 7;
    const float* wr = w + k * 7;
    float acc = b[k];
#pragma unroll
    for (int j = 0; j < 7; j++) acc += er[j] * wr[j];
    g_t[idx] = fmaxf(acc, 0.f);
}

// Transpose GRU weights: wihT[j*192+g] = wih[g*64+j]
__global__ void transpose_gru_kernel(const float* __restrict__ wih, const float* __restrict__ whh) {
    int idx = blockIdx.x * blockDim.x + threadIdx.x;
    if (idx >= 192 * 64) return;
    int g = idx / 64, j = idx % 64;
    g_wihT[j * 192 + g] = wih[idx];
    g_whhT[j * 192 + g] = whh[idx];
}

// ---------------- we = t @ em2_w.T + em2_b  (M=E, N=4096, K=64) -------------
// 128x128 tile, 256 threads, 8x8 microtile, smem [k][m] padded stride 132.
__global__ __launch_bounds__(256, 2) void we_gemm(const float* __restrict__ B,
                                                  const float* __restrict__ bias) {
    extern __shared__ float sm[];
    float* As = sm;                 // [64][132]
    float* Bs = sm + 64 * 132;      // [64][132]
    int tid = threadIdx.x;
    size_t m0 = (size_t)blockIdx.x * 128;
    int n0 = blockIdx.y * 128;
#pragma unroll
    for (int i = 0; i < 8; i++) {
        int idx = i * 256 + tid;        // 0..2047
        int r = idx >> 4;               // 0..127
        int k4 = (idx & 15) << 2;       // 0..60
        float4 av = *(const float4*)(g_t + (m0 + r) * 64 + k4);
        float4 bv = *(const float4*)(B + (size_t)(n0 + r) * 64 + k4);
        As[(k4 + 0) * 132 + r] = av.x;
        As[(k4 + 1) * 132 + r] = av.y;
        As[(k4 + 2) * 132 + r] = av.z;
        As[(k4 + 3) * 132 + r] = av.w;
        Bs[(k4 + 0) * 132 + r] = bv.x;
        Bs[(k4 + 1) * 132 + r] = bv.y;
        Bs[(k4 + 2) * 132 + r] = bv.z;
        Bs[(k4 + 3) * 132 + r] = bv.w;
    }
    __syncthreads();
    int tx = tid & 15, ty = tid >> 4;
    float acc[8][8];
#pragma unroll
    for (int i = 0; i < 8; i++)
#pragma unroll
        for (int j = 0; j < 8; j++) acc[i][j] = 0.f;
    const float* Ab = As + ty * 8;
    const float* Bb = Bs + tx * 8;
#pragma unroll 4
    for (int k = 0; k < 64; k++) {
        float4 a0 = *(const float4*)(Ab + k * 132);
        float4 a1 = *(const float4*)(Ab + k * 132 + 4);
        float4 b0 = *(const float4*)(Bb + k * 132);
        float4 b1 = *(const float4*)(Bb + k * 132 + 4);
        float av[8] = {a0.x, a0.y, a0.z, a0.w, a1.x, a1.y, a1.z, a1.w};
        float bv[8] = {b0.x, b0.y, b0.z, b0.w, b1.x, b1.y, b1.z, b1.w};
#pragma unroll
        for (int ii = 0; ii < 8; ii++)
#pragma unroll
            for (int jj = 0; jj < 8; jj++) acc[ii][jj] += av[ii] * bv[jj];
    }
    float bb[8];
#pragma unroll
    for (int jj = 0; jj < 8; jj++) bb[jj] = bias[n0 + tx * 8 + jj];
#pragma unroll
    for (int ii = 0; ii < 8; ii++) {
        size_t row = m0 + ty * 8 + ii;
        float* dst = g_we + row * 4096 + n0 + tx * 8;
        float4 v0 = make_float4(acc[ii][0] + bb[0], acc[ii][1] + bb[1],
                                acc[ii][2] + bb[2], acc[ii][3] + bb[3]);
        float4 v1 = make_float4(acc[ii][4] + bb[4], acc[ii][5] + bb[5],
                                acc[ii][6] + bb[6], acc[ii][7] + bb[7]);
        *(float4*)dst = v0;
        *(float4*)(dst + 4) = v1;
    }
}

__global__ void zero_agg_kernel() {
    int idx = blockIdx.x * blockDim.x + threadIdx.x;
    if (idx < NMAX * DIM) g_agg[idx] = 0.f;
}

// msg[e] = out[src[e]] @ we[e]; scatter-add into agg[dst[e]]. One warp per edge.
__global__ void msg_kernel(const int* __restrict__ ei, int e) {
    int eid = (blockIdx.x * blockDim.x + threadIdx.x) >> 5;
    int l = threadIdx.x & 31;
    if (eid >= e) return;
    int s = ei[eid], d = ei[e + eid];
    float2 myo = *(const float2*)(g_out + (size_t)s * 64 + 2 * l);
    const float2* wrow = (const float2*)(g_we + (size_t)eid * 4096) + l;
    float ax = 0.f, ay = 0.f;
#pragma unroll
    for (int i = 0; i < 64; i++) {
        float oi = __shfl_sync(0xffffffffu, (i & 1) ? myo.y : myo.x, i >> 1);
        float2 wv = wrow[i * 32];
        ax += oi * wv.x;
        ay += oi * wv.y;
    }
    atomicAdd(&g_agg[(size_t)d * 64 + 2 * l], ax);
    atomicAdd(&g_agg[(size_t)d * 64 + 2 * l + 1], ay);
}

// acci[g] = bih + Wih m, acch[g] = bhh + Whh h (transposed weights, coalesced)
__device__ __forceinline__ void gate_mm(int off, int l, const float4* msw, const float4* hsw,
                                        const float* __restrict__ bih,
                                        const float* __restrict__ bhh,
                                        float2 acci[4], float2 acch[4]) {
    float2 bi = *(const float2*)(bih + off + 2 * l);
    float2 bh = *(const float2*)(bhh + off + 2 * l);
#pragma unroll
    for (int t = 0; t < 4; t++) { acci[t] = bi; acch[t] = bh; }
#pragma unroll 8
    for (int j = 0; j < 64; j++) {
        float2 wi = *(const float2*)(g_wihT + j * 192 + off + 2 * l);
        float2 wh = *(const float2*)(g_whhT + j * 192 + off + 2 * l);
        float4 mv = msw[j];
        float4 hv = hsw[j];
        acci[0].x += mv.x * wi.x; acci[0].y += mv.x * wi.y;
        acci[1].x += mv.y * wi.x; acci[1].y += mv.y * wi.y;
        acci[2].x += mv.z * wi.x; acci[2].y += mv.z * wi.y;
        acci[3].x += mv.w * wi.x; acci[3].y += mv.w * wi.y;
        acch[0].x += hv.x * wh.x; acch[0].y += hv.x * wh.y;
        acch[1].x += hv.y * wh.x; acch[1].y += hv.y * wh.y;
        acch[2].x += hv.z * wh.x; acch[2].y += hv.z * wh.y;
        acch[3].x += hv.w * wh.x; acch[3].y += hv.w * wh.y;
    }
}

// Fused: m = relu(out@root_w + agg*inv_deg + conv_b); GRU step; out=h (in place).
// One warp handles 4 nodes. Block = 8 warps = 32 nodes.
__global__ __launch_bounds__(256) void gru_kernel(const float* __restrict__ root_w,
                                                  const float* __restrict__ conv_b,
                                                  const float* __restrict__ bih,
                                                  const float* __restrict__ bhh, int n) {
    __shared__ float4 hs[8][64];
    __shared__ float4 ms[8][64];
    int w = threadIdx.x >> 5, l = threadIdx.x & 31;
    int n0 = (blockIdx.x * 8 + w) * 4;
    float2 h[4];
#pragma unroll
    for (int t = 0; t < 4; t++)
        h[t] = *(const float2*)(g_out + (size_t)(n0 + t) * 64 + 2 * l);
    hs[w][2 * l]     = make_float4(h[0].x, h[1].x, h[2].x, h[3].x);
    hs[w][2 * l + 1] = make_float4(h[0].y, h[1].y, h[2].y, h[3].y);

    float2 cb = *(const float2*)(conv_b + 2 * l);
    float2 m[4];
#pragma unroll
    for (int t = 0; t < 4; t++) {
        float d = g_deg[n0 + t];
        float inv = d > 0.f ? 1.f / d : 0.f;
        float2 a = *(const float2*)(g_agg + (size_t)(n0 + t) * 64 + 2 * l);
        m[t].x = cb.x + a.x * inv;
        m[t].y = cb.y + a.y * inv;
    }
    __syncwarp();
#pragma unroll 8
    for (int i = 0; i < 64; i++) {
        float2 wv = *(const float2*)(root_w + i * 64 + 2 * l);
        float4 hv = hs[w][i];
        m[0].x += hv.x * wv.x; m[0].y += hv.x * wv.y;
        m[1].x += hv.y * wv.x; m[1].y += hv.y * wv.y;
        m[2].x += hv.z * wv.x; m[2].y += hv.z * wv.y;
        m[3].x += hv.w * wv.x; m[3].y += hv.w * wv.y;
    }
#pragma unroll
    for (int t = 0; t < 4; t++) { m[t].x = fmaxf(m[t].x, 0.f); m[t].y = fmaxf(m[t].y, 0.f); }
    ms[w][2 * l]     = make_float4(m[0].x, m[1].x, m[2].x, m[3].x);
    ms[w][2 * l + 1] = make_float4(m[0].y, m[1].y, m[2].y, m[3].y);
    __syncwarp();

    float2 acci[4], acch[4], r[4], z[4];
    gate_mm(0, l, ms[w], hs[w], bih, bhh, acci, acch);
#pragma unroll
    for (int t = 0; t < 4; t++) {
        r[t].x = sigmoidf(acci[t].x + acch[t].x);
        r[t].y = sigmoidf(acci[t].y + acch[t].y);
    }
    gate_mm(64, l, ms[w], hs[w], bih, bhh, acci, acch);
#pragma unroll
    for (int t = 0; t < 4; t++) {
        z[t].x = sigmoidf(acci[t].x + acch[t].x);
        z[t].y = sigmoidf(acci[t].y + acch[t].y);
    }
    gate_mm(128, l, ms[w], hs[w], bih, bhh, acci, acch);
#pragma unroll
    for (int t = 0; t < 4; t++) {
        float ncx = tanhf(acci[t].x + r[t].x * acch[t].x);
        float ncy = tanhf(acci[t].y + r[t].y * acch[t].y);
        float2 hn;
        hn.x = (1.f - z[t].x) * ncx + z[t].x * h[t].x;
        hn.y = (1.f - z[t].y) * ncy + z[t].y * h[t].y;
        *(float2*)(g_out + (size_t)(n0 + t) * 64 + 2 * l) = hn;
    }
    (void)n;
}

// ---------------- Set2Set ----------------------------------------------------
__global__ void lstm_kernel(const float* __restrict__ wih, const float* __restrict__ whh,
                            const float* __restrict__ bih, const float* __restrict__ bhh) {
    __shared__ float qs[128], hls[64], gs[256];
    int t = threadIdx.x;
    if (t < 128) qs[t] = g_qstar[t];
    if (t < 64) hls[t] = g_hl[t];
    __syncthreads();
    float acc = bih[t] + bhh[t];
    const float* wi = wih + t * 128;
#pragma unroll 8
    for (int j = 0; j < 128; j++) acc += wi[j] * qs[j];
    const float* wh = whh + t * 64;
#pragma unroll 8
    for (int j = 0; j < 64; j++) acc += wh[j] * hls[j];
    gs[t] = acc;
    __syncthreads();
    if (t < 64) {
        float ig = sigmoidf(gs[t]);
        float fg = sigmoidf(gs[64 + t]);
        float gg = tanhf(gs[128 + t]);
        float og = sigmoidf(gs[192 + t]);
        float c = fg * g_cl[t] + ig * gg;
        g_cl[t] = c;
        float hv = og * tanhf(c);
        g_hl[t] = hv;
        g_q[t] = hv;
    }
    if (t == 64) { g_sumexp = 0.f; g_emax = -1e30f; }
    if (t >= 128 && t < 192) g_r[t - 128] = 0.f;
}

// pass A: logits e[n] = out[n].q ; global max
__global__ void attn_a_kernel(int n) {
    __shared__ float wmax[8];
    int gw = (blockIdx.x * blockDim.x + threadIdx.x) >> 5;
    int l = threadIdx.x & 31;
    int nw = (gridDim.x * blockDim.x) >> 5;
    float2 q2 = *(const float2*)(g_q + 2 * l);
    float lmax = -1e30f;
    for (int i = gw; i < n; i += nw) {
        float2 o2 = *(const float2*)(g_out + (size_t)i * 64 + 2 * l);
        float d = o2.x * q2.x + o2.y * q2.y;
#pragma unroll
        for (int off = 16; off; off >>= 1) d += __shfl_xor_sync(0xffffffffu, d, off);
        if (l == 0) g_e[i] = d;
        lmax = fmaxf(lmax, d);
    }
    if (l == 0) wmax[threadIdx.x >> 5] = lmax;
    __syncthreads();
    if (threadIdx.x < 8) {
        float v = wmax[threadIdx.x];
#pragma unroll
        for (int off = 4; off; off >>= 1) v = fmaxf(v, __shfl_xor_sync(0xffu, v, off));
        if (threadIdx.x == 0) atomicMaxF(&g_emax, v);
    }
}

// pass B: w = exp(e - max); r += w*out; sumexp += w
__global__ void attn_b_kernel(int n) {
    __shared__ float rs[64];
    __shared__ float ssum;
    int tid = threadIdx.x;
    if (tid < 64) rs[tid] = 0.f;
    if (tid == 64) ssum = 0.f;
    __syncthreads();
    int gw = (blockIdx.x * blockDim.x + tid) >> 5;
    int l = tid & 31;
    int nw = (gridDim.x * blockDim.x) >> 5;
    float emax = g_emax;
    float rx = 0.f, ry = 0.f, s = 0.f;
    for (int i = gw; i < n; i += nw) {
        float wgt = expf(g_e[i] - emax);
        float2 o2 = *(const float2*)(g_out + (size_t)i * 64 + 2 * l);
        rx += wgt * o2.x;
        ry += wgt * o2.y;
        if (l == 0) s += wgt;
    }
    atomicAdd(&rs[2 * l], rx);
    atomicAdd(&rs[2 * l + 1], ry);
    if (l == 0) atomicAdd(&ssum, s);
    __syncthreads();
    if (tid < 64) atomicAdd(&g_r[tid], rs[tid]);
    if (tid == 64) atomicAdd(&g_sumexp, ssum);
}

__global__ void s2s_fin_kernel() {
    int t = threadIdx.x;
    if (t < 64) {
        g_qstar[t] = g_q[t];
        g_qstar[64 + t] = g_r[t] / g_sumexp;
    }
}

__global__ void final_kernel(const float* __restrict__ lin1_w, const float* __restrict__ lin1_b,
                             const float* __restrict__ lin3_w, const float* __restrict__ lin3_b,
                             float* __restrict__ out) {
    __shared__ float qs[128];
    __shared__ float red[2];
    int t = threadIdx.x;  // 64 threads
    qs[t] = g_qstar[t];
    qs[64 + t] = g_qstar[64 + t];
    __syncthreads();
    float acc = lin1_b[t];
    const float* wr = lin1_w + t * 128;
#pragma unroll 8
    for (int j = 0; j < 128; j++) acc += qs[j] * wr[j];
    acc = fmaxf(acc, 0.f);
    float v = acc * lin3_w[t];
#pragma unroll
    for (int off = 16; off; off >>= 1) v += __shfl_xor_sync(0xffffffffu, v, off);
    if ((t & 31) == 0) red[t >> 5] = v;
    __syncthreads();
    if (t == 0) out[0] = red[0] + red[1] + lin3_b[0];
}

// ---------------- launch ------------------------------------------------------
extern "C" void kernel_launch(void* const* d_in, const int* in_sizes, int n_in,
                              void* d_out, int out_size) {
    const float* x        = (const float*)d_in[0];
    const float* edge_attr= (const float*)d_in[1];
    const int*   ei       = (const int*)d_in[2];
    const float* lin0_w   = (const float*)d_in[4];
    const float* lin0_b   = (const float*)d_in[5];
    const float* em1_w    = (const float*)d_in[6];
    const float* em1_b    = (const float*)d_in[7];
    const float* em2_w    = (const float*)d_in[8];
    const float* em2_b    = (const float*)d_in[9];
    const float* root_w   = (const float*)d_in[10];
    const float* conv_b   = (const float*)d_in[11];
    const float* gru_wih  = (const float*)d_in[12];
    const float* gru_whh  = (const float*)d_in[13];
    const float* gru_bih  = (const float*)d_in[14];
    const float* gru_bhh  = (const float*)d_in[15];
    const float* lstm_wih = (const float*)d_in[16];
    const float* lstm_whh = (const float*)d_in[17];
    const float* lstm_bih = (const float*)d_in[18];
    const float* lstm_bhh = (const float*)d_in[19];
    const float* lin1_w   = (const float*)d_in[20];
    const float* lin1_b   = (const float*)d_in[21];
    const float* lin3_w   = (const float*)d_in[22];
    const float* lin3_b   = (const float*)d_in[23];

    int n = in_sizes[0] / 3;
    int e = in_sizes[2] / 2;
    if (n > NMAX || e > EMAX) return;

    cudaFuncSetAttribute(we_gemm, cudaFuncAttributeMaxDynamicSharedMemorySize, GEMM_SMEM);

    init_kernel<<<(NMAX + 255) / 256, 256>>>();
    deg_kernel<<<(e + 255) / 256, 256>>>(ei, e);
    lin0_kernel<<<(n * DIM + 255) / 256, 256>>>(x, lin0_w, lin0_b, n);
    edge_mlp1_kernel<<<(e * DIM + 255) / 256, 256>>>(edge_attr, em1_w, em1_b, e);
    transpose_gru_kernel<<<(192 * 64 + 255) / 256, 256>>>(gru_wih, gru_whh);

    int mtiles = (e + 127) / 128;
    we_gemm<<<dim3(mtiles, 32), 256, GEMM_SMEM>>>(em2_w, em2_b);

    for (int it = 0; it < 6; it++) {
        zero_agg_kernel<<<(NMAX * DIM + 255) / 256, 256>>>();
        msg_kernel<<<(e * 32 + 255) / 256, 256>>>(ei, e);
        gru_kernel<<<(n + 31) / 32, 256>>>(root_w, conv_b, gru_bih, gru_bhh, n);
    }

    for (int it = 0; it < 6; it++) {
        lstm_kernel<<<1, 256>>>(lstm_wih, lstm_whh, lstm_bih, lstm_bhh);
        attn_a_kernel<<<120, 256>>>(n);
        attn_b_kernel<<<120, 256>>>(n);
        s2s_fin_kernel<<<1, 64>>>();
    }

    final_kernel<<<1, 64>>>(lin1_w, lin1_b, lin3_w, lin3_b, (float*)d_out);
}

// round 17
// speedup vs baseline: 1.7374x; 1.7374x over previous
#include <cuda_runtime.h>
#include <cuda_fp16.h>
#include <math.h>

// Problem constants (padded)
#define DIM   64
#define NMAX  10016              // 313 blocks * 32 nodes
#define EMAX  40064              // 313 tiles * 128 rows

// ---------------- scratch (device globals; no allocation allowed) ----------
__device__ __align__(128) float  g_out[NMAX * DIM];        // h == out
__device__ __align__(128) float  g_agg[NMAX * DIM];
__device__ __align__(128) float  g_deg[NMAX];
__device__ __align__(128) __half g_t_h[EMAX * DIM];        // edge MLP hidden (fp16)
__device__ __align__(128) __half g_em2h[4096 * 64];        // em2_w in fp16
__device__ __align__(128) __half g_we_h[(size_t)EMAX * 4096]; // edge weights fp16, 328MB
__device__ __align__(128) float  g_wihT[64 * 192];
__device__ __align__(128) float  g_whhT[64 * 192];
__device__ __align__(128) float  g_hl[64];
__device__ __align__(128) float  g_cl[64];
__device__ __align__(128) float  g_q[64];
__device__ __align__(128) float  g_r[64];
__device__ __align__(128) float  g_e[NMAX];
__device__ float g_sumexp;
__device__ float g_emax;

__device__ __forceinline__ float sigmoidf(float x) { return 1.f / (1.f + expf(-x)); }

__device__ __forceinline__ void atomicMaxF(float* addr, float val) {
    int old = __float_as_int(*addr);
    while (__int_as_float(old) < val) {
        int prev = atomicCAS((int*)addr, old, __float_as_int(val));
        if (prev == old) break;
        old = prev;
    }
}

// ---------------- init: zero deg + set2set state ----------------------------
__global__ void init_kernel() {
    int idx = blockIdx.x * blockDim.x + threadIdx.x;
    if (idx < NMAX) g_deg[idx] = 0.f;
    if (idx < 64) { g_hl[idx] = 0.f; g_cl[idx] = 0.f; }
}

__global__ void deg_kernel(const int* __restrict__ ei, int e) {
    int idx = blockIdx.x * blockDim.x + threadIdx.x;
    if (idx < e) atomicAdd(&g_deg[ei[e + idx]], 1.f);
}

// out = relu(x @ lin0_w.T + b)
__global__ void lin0_kernel(const float* __restrict__ x, const float* __restrict__ w,
                            const float* __restrict__ b, int n) {
    int idx = blockIdx.x * blockDim.x + threadIdx.x;
    if (idx >= n * DIM) return;
    int node = idx >> 6, o = idx & 63;
    const float* xr = x + node * 3;
    float acc = b[o] + xr[0] * w[o * 3 + 0] + xr[1] * w[o * 3 + 1] + xr[2] * w[o * 3 + 2];
    g_out[idx] = fmaxf(acc, 0.f);
}

// t = relu(edge_attr @ em1_w.T + em1_b)  -> fp16
__global__ void edge_mlp1_kernel(const float* __restrict__ ea, const float* __restrict__ w,
                                 const float* __restrict__ b, int e) {
    int idx = blockIdx.x * blockDim.x + threadIdx.x;
    if (idx >= e * DIM) return;
    int ed = idx >> 6, k = idx & 63;
    const float* er = ea + ed * 7;
    const float* wr = w + k * 7;
    float acc = b[k];
#pragma unroll
    for (int j = 0; j < 7; j++) acc += er[j] * wr[j];
    g_t_h[idx] = __float2half_rn(fmaxf(acc, 0.f));
}

// em2_w fp32 -> fp16
__global__ void em2_convert_kernel(const float* __restrict__ w) {
    int idx = blockIdx.x * blockDim.x + threadIdx.x;
    if (idx < 4096 * 64) g_em2h[idx] = __float2half_rn(w[idx]);
}

// Transpose GRU weights: wihT[j*192+g] = wih[g*64+j]
__global__ void transpose_gru_kernel(const float* __restrict__ wih, const float* __restrict__ whh) {
    int idx = blockIdx.x * blockDim.x + threadIdx.x;
    if (idx >= 192 * 64) return;
    int g = idx / 64, j = idx % 64;
    g_wihT[j * 192 + g] = wih[idx];
    g_whhT[j * 192 + g] = whh[idx];
}

// ---------------- we = t @ em2_w.T + em2_b  (M=E, N=4096, K=64), fp16 HMMA ---
// Block: 128x128 tile, 256 threads = 8 warps (4 m x 2 n), warp tile 32x64.
// mma.sync m16n8k16 row.col f32 accum, fp16 in/out.
// Smem: As[128][72], Bs[128][72] halfs (stride 72 -> conflict-free frag loads).
// Epilogue staged through smem [128][136] for coalesced 256B global stores.
__global__ __launch_bounds__(256) void we_gemm(const float* __restrict__ bias) {
    __shared__ __align__(16) __half sm[2 * 128 * 72];   // 36864 B
    __half* As = sm;
    __half* Bs = sm + 128 * 72;
    int tid = threadIdx.x;
    size_t m0 = (size_t)blockIdx.x * 128;
    int bn0 = blockIdx.y * 128;

#pragma unroll
    for (int i = 0; i < 4; i++) {
        int idx = i * 256 + tid;           // 0..1023
        int r = idx >> 3, c = idx & 7;     // row 0..127, int4 chunk 0..7
        ((int4*)(As + r * 72))[c] = ((const int4*)(g_t_h + (m0 + r) * 64))[c];
        ((int4*)(Bs + r * 72))[c] = ((const int4*)(g_em2h + (size_t)(bn0 + r) * 64))[c];
    }
    __syncthreads();

    int w = tid >> 5, l = tid & 31;
    int m0w = (w & 3) * 32;        // warp rows within tile
    int n0w = (w >> 2) * 64;       // warp cols within tile
    int g = l >> 2, tg = l & 3;

    float acc[2][8][4];
#pragma unroll
    for (int mf = 0; mf < 2; mf++)
#pragma unroll
        for (int nf = 0; nf < 8; nf++)
#pragma unroll
            for (int q = 0; q < 4; q++) acc[mf][nf][q] = 0.f;

#pragma unroll
    for (int ks = 0; ks < 4; ks++) {
        int k0 = ks * 16;
        unsigned a[2][4];
#pragma unroll
        for (int mf = 0; mf < 2; mf++) {
            const __half* p = As + (m0w + mf * 16 + g) * 72 + k0 + 2 * tg;
            a[mf][0] = *(const unsigned*)p;
            a[mf][1] = *(const unsigned*)(p + 8 * 72);
            a[mf][2] = *(const unsigned*)(p + 8);
            a[mf][3] = *(const unsigned*)(p + 8 * 72 + 8);
        }
#pragma unroll
        for (int nf = 0; nf < 8; nf++) {
            const __half* q = Bs + (n0w + nf * 8 + g) * 72 + k0 + 2 * tg;
            unsigned b0 = *(const unsigned*)q;
            unsigned b1 = *(const unsigned*)(q + 8);
#pragma unroll
            for (int mf = 0; mf < 2; mf++) {
                asm volatile(
                    "mma.sync.aligned.m16n8k16.row.col.f32.f16.f16.f32 "
                    "{%0,%1,%2,%3}, {%4,%5,%6,%7}, {%8,%9}, {%0,%1,%2,%3};"
                    : "+f"(acc[mf][nf][0]), "+f"(acc[mf][nf][1]),
                      "+f"(acc[mf][nf][2]), "+f"(acc[mf][nf][3])
                    : "r"(a[mf][0]), "r"(a[mf][1]), "r"(a[mf][2]), "r"(a[mf][3]),
                      "r"(b0), "r"(b1));
            }
        }
    }
    __syncthreads();   // done reading As/Bs; reuse smem for epilogue

    __half* Cs = sm;   // [128][136] halfs = 34816 B
#pragma unroll
    for (int mf = 0; mf < 2; mf++) {
#pragma unroll
        for (int nf = 0; nf < 8; nf++) {
            int row = m0w + mf * 16 + g;
            int col = n0w + nf * 8 + 2 * tg;
            float bx = bias[bn0 + col], by = bias[bn0 + col + 1];
            *(__half2*)(Cs + row * 136 + col) =
                __floats2half2_rn(acc[mf][nf][0] + bx, acc[mf][nf][1] + by);
            *(__half2*)(Cs + (row + 8) * 136 + col) =
                __floats2half2_rn(acc[mf][nf][2] + bx, acc[mf][nf][3] + by);
        }
    }
    __syncthreads();

#pragma unroll
    for (int i = 0; i < 8; i++) {
        int idx = i * 256 + tid;           // 0..2047
        int row = idx >> 4, chunk = idx & 15;
        int4 v = *(const int4*)(Cs + row * 136 + chunk * 8);
        *(int4*)(g_we_h + (m0 + row) * 4096 + bn0 + chunk * 8) = v;
    }
}

__global__ void zero_agg_kernel() {
    int idx = blockIdx.x * blockDim.x + threadIdx.x;
    if (idx < NMAX * DIM) g_agg[idx] = 0.f;
}

// msg[e] = out[src[e]] @ we[e]; scatter-add into agg[dst[e]]. One warp per edge.
__global__ void msg_kernel(const int* __restrict__ ei, int e) {
    int eid = (blockIdx.x * blockDim.x + threadIdx.x) >> 5;
    int l = threadIdx.x & 31;
    if (eid >= e) return;
    int s = ei[eid], d = ei[e + eid];
    float2 myo = *(const float2*)(g_out + (size_t)s * 64 + 2 * l);
    const __half2* wrow = (const __half2*)(g_we_h + (size_t)eid * 4096) + l;
    float ax = 0.f, ay = 0.f;
#pragma unroll
    for (int i = 0; i < 64; i++) {
        float oi = __shfl_sync(0xffffffffu, (i & 1) ? myo.y : myo.x, i >> 1);
        float2 wv = __half22float2(wrow[i * 32]);
        ax += oi * wv.x;
        ay += oi * wv.y;
    }
    atomicAdd(&g_agg[(size_t)d * 64 + 2 * l], ax);
    atomicAdd(&g_agg[(size_t)d * 64 + 2 * l + 1], ay);
}

// acci[g] = bih + Wih m, acch[g] = bhh + Whh h (transposed weights, coalesced)
__device__ __forceinline__ void gate_mm(int off, int l, const float4* msw, const float4* hsw,
                                        const float* __restrict__ bih,
                                        const float* __restrict__ bhh,
                                        float2 acci[4], float2 acch[4]) {
    float2 bi = *(const float2*)(bih + off + 2 * l);
    float2 bh = *(const float2*)(bhh + off + 2 * l);
#pragma unroll
    for (int t = 0; t < 4; t++) { acci[t] = bi; acch[t] = bh; }
#pragma unroll 8
    for (int j = 0; j < 64; j++) {
        float2 wi = *(const float2*)(g_wihT + j * 192 + off + 2 * l);
        float2 wh = *(const float2*)(g_whhT + j * 192 + off + 2 * l);
        float4 mv = msw[j];
        float4 hv = hsw[j];
        acci[0].x += mv.x * wi.x; acci[0].y += mv.x * wi.y;
        acci[1].x += mv.y * wi.x; acci[1].y += mv.y * wi.y;
        acci[2].x += mv.z * wi.x; acci[2].y += mv.z * wi.y;
        acci[3].x += mv.w * wi.x; acci[3].y += mv.w * wi.y;
        acch[0].x += hv.x * wh.x; acch[0].y += hv.x * wh.y;
        acch[1].x += hv.y * wh.x; acch[1].y += hv.y * wh.y;
        acch[2].x += hv.z * wh.x; acch[2].y += hv.z * wh.y;
        acch[3].x += hv.w * wh.x; acch[3].y += hv.w * wh.y;
    }
}

// Fused: m = relu(out@root_w + agg*inv_deg + conv_b); GRU step; out=h (in place).
// One warp handles 4 nodes. Block = 8 warps = 32 nodes.
__global__ __launch_bounds__(256) void gru_kernel(const float* __restrict__ root_w,
                                                  const float* __restrict__ conv_b,
                                                  const float* __restrict__ bih,
                                                  const float* __restrict__ bhh, int n) {
    __shared__ float4 hs[8][64];
    __shared__ float4 ms[8][64];
    int w = threadIdx.x >> 5, l = threadIdx.x & 31;
    int n0 = (blockIdx.x * 8 + w) * 4;
    float2 h[4];
#pragma unroll
    for (int t = 0; t < 4; t++)
        h[t] = *(const float2*)(g_out + (size_t)(n0 + t) * 64 + 2 * l);
    hs[w][2 * l]     = make_float4(h[0].x, h[1].x, h[2].x, h[3].x);
    hs[w][2 * l + 1] = make_float4(h[0].y, h[1].y, h[2].y, h[3].y);

    float2 cb = *(const float2*)(conv_b + 2 * l);
    float2 m[4];
#pragma unroll
    for (int t = 0; t < 4; t++) {
        float d = g_deg[n0 + t];
        float inv = d > 0.f ? 1.f / d : 0.f;
        float2 a = *(const float2*)(g_agg + (size_t)(n0 + t) * 64 + 2 * l);
        m[t].x = cb.x + a.x * inv;
        m[t].y = cb.y + a.y * inv;
    }
    __syncwarp();
#pragma unroll 8
    for (int i = 0; i < 64; i++) {
        float2 wv = *(const float2*)(root_w + i * 64 + 2 * l);
        float4 hv = hs[w][i];
        m[0].x += hv.x * wv.x; m[0].y += hv.x * wv.y;
        m[1].x += hv.y * wv.x; m[1].y += hv.y * wv.y;
        m[2].x += hv.z * wv.x; m[2].y += hv.z * wv.y;
        m[3].x += hv.w * wv.x; m[3].y += hv.w * wv.y;
    }
#pragma unroll
    for (int t = 0; t < 4; t++) { m[t].x = fmaxf(m[t].x, 0.f); m[t].y = fmaxf(m[t].y, 0.f); }
    ms[w][2 * l]     = make_float4(m[0].x, m[1].x, m[2].x, m[3].x);
    ms[w][2 * l + 1] = make_float4(m[0].y, m[1].y, m[2].y, m[3].y);
    __syncwarp();

    float2 acci[4], acch[4], r[4], z[4];
    gate_mm(0, l, ms[w], hs[w], bih, bhh, acci, acch);
#pragma unroll
    for (int t = 0; t < 4; t++) {
        r[t].x = sigmoidf(acci[t].x + acch[t].x);
        r[t].y = sigmoidf(acci[t].y + acch[t].y);
    }
    gate_mm(64, l, ms[w], hs[w], bih, bhh, acci, acch);
#pragma unroll
    for (int t = 0; t < 4; t++) {
        z[t].x = sigmoidf(acci[t].x + acch[t].x);
        z[t].y = sigmoidf(acci[t].y + acch[t].y);
    }
    gate_mm(128, l, ms[w], hs[w], bih, bhh, acci, acch);
#pragma unroll
    for (int t = 0; t < 4; t++) {
        float ncx = tanhf(acci[t].x + r[t].x * acch[t].x);
        float ncy = tanhf(acci[t].y + r[t].y * acch[t].y);
        float2 hn;
        hn.x = (1.f - z[t].x) * ncx + z[t].x * h[t].x;
        hn.y = (1.f - z[t].y) * ncy + z[t].y * h[t].y;
        *(float2*)(g_out + (size_t)(n0 + t) * 64 + 2 * l) = hn;
    }
    (void)n;
}

// ---------------- Set2Set ----------------------------------------------------
// q_star is recomputed from (g_q, g_r, g_sumexp) of the previous iteration.
__global__ void lstm_kernel(const float* __restrict__ wih, const float* __restrict__ whh,
                            const float* __restrict__ bih, const float* __restrict__ bhh,
                            int first) {
    __shared__ float qs[128], hls[64], gs[256];
    int t = threadIdx.x;
    if (t < 64) {
        qs[t] = first ? 0.f : g_q[t];
        qs[64 + t] = first ? 0.f : g_r[t] / g_sumexp;
        hls[t] = g_hl[t];
    }
    __syncthreads();
    float acc = bih[t] + bhh[t];
    const float* wi = wih + t * 128;
#pragma unroll 8
    for (int j = 0; j < 128; j++) acc += wi[j] * qs[j];
    const float* wh = whh + t * 64;
#pragma unroll 8
    for (int j = 0; j < 64; j++) acc += wh[j] * hls[j];
    gs[t] = acc;
    __syncthreads();
    if (t < 64) {
        float ig = sigmoidf(gs[t]);
        float fg = sigmoidf(gs[64 + t]);
        float gg = tanhf(gs[128 + t]);
        float og = sigmoidf(gs[192 + t]);
        float c = fg * g_cl[t] + ig * gg;
        g_cl[t] = c;
        float hv = og * tanhf(c);
        g_hl[t] = hv;
        g_q[t] = hv;
    }
    if (t == 64) { g_sumexp = 0.f; g_emax = -1e30f; }
    if (t >= 128 && t < 192) g_r[t - 128] = 0.f;
}

// pass A: logits e[n] = out[n].q ; global max
__global__ void attn_a_kernel(int n) {
    __shared__ float wmax[8];
    int gw = (blockIdx.x * blockDim.x + threadIdx.x) >> 5;
    int l = threadIdx.x & 31;
    int nw = (gridDim.x * blockDim.x) >> 5;
    float2 q2 = *(const float2*)(g_q + 2 * l);
    float lmax = -1e30f;
    for (int i = gw; i < n; i += nw) {
        float2 o2 = *(const float2*)(g_out + (size_t)i * 64 + 2 * l);
        float d = o2.x * q2.x + o2.y * q2.y;
#pragma unroll
        for (int off = 16; off; off >>= 1) d += __shfl_xor_sync(0xffffffffu, d, off);
        if (l == 0) g_e[i] = d;
        lmax = fmaxf(lmax, d);
    }
    if (l == 0) wmax[threadIdx.x >> 5] = lmax;
    __syncthreads();
    if (threadIdx.x < 8) {
        float v = wmax[threadIdx.x];
#pragma unroll
        for (int off = 4; off; off >>= 1) v = fmaxf(v, __shfl_xor_sync(0xffu, v, off));
        if (threadIdx.x == 0) atomicMaxF(&g_emax, v);
    }
}

// pass B: w = exp(e - max); r += w*out; sumexp += w
__global__ void attn_b_kernel(int n) {
    __shared__ float rs[64];
    __shared__ float ssum;
    int tid = threadIdx.x;
    if (tid < 64) rs[tid] = 0.f;
    if (tid == 64) ssum = 0.f;
    __syncthreads();
    int gw = (blockIdx.x * blockDim.x + tid) >> 5;
    int l = tid & 31;
    int nw = (gridDim.x * blockDim.x) >> 5;
    float emax = g_emax;
    float rx = 0.f, ry = 0.f, s = 0.f;
    for (int i = gw; i < n; i += nw) {
        float wgt = expf(g_e[i] - emax);
        float2 o2 = *(const float2*)(g_out + (size_t)i * 64 + 2 * l);
        rx += wgt * o2.x;
        ry += wgt * o2.y;
        if (l == 0) s += wgt;
    }
    atomicAdd(&rs[2 * l], rx);
    atomicAdd(&rs[2 * l + 1], ry);
    if (l == 0) atomicAdd(&ssum, s);
    __syncthreads();
    if (tid < 64) atomicAdd(&g_r[tid], rs[tid]);
    if (tid == 64) atomicAdd(&g_sumexp, ssum);
}

__global__ void final_kernel(const float* __restrict__ lin1_w, const float* __restrict__ lin1_b,
                             const float* __restrict__ lin3_w, const float* __restrict__ lin3_b,
                             float* __restrict__ out) {
    __shared__ float qs[128];
    __shared__ float red[2];
    int t = threadIdx.x;  // 64 threads
    qs[t] = g_q[t];
    qs[64 + t] = g_r[t] / g_sumexp;
    __syncthreads();
    float acc = lin1_b[t];
    const float* wr = lin1_w + t * 128;
#pragma unroll 8
    for (int j = 0; j < 128; j++) acc += qs[j] * wr[j];
    acc = fmaxf(acc, 0.f);
    float v = acc * lin3_w[t];
#pragma unroll
    for (int off = 16; off; off >>= 1) v += __shfl_xor_sync(0xffffffffu, v, off);
    if ((t & 31) == 0) red[t >> 5] = v;
    __syncthreads();
    if (t == 0) out[0] = red[0] + red[1] + lin3_b[0];
}

// ---------------- launch ------------------------------------------------------
extern "C" void kernel_launch(void* const* d_in, const int* in_sizes, int n_in,
                              void* d_out, int out_size) {
    const float* x        = (const float*)d_in[0];
    const float* edge_attr= (const float*)d_in[1];
    const int*   ei       = (const int*)d_in[2];
    const float* lin0_w   = (const float*)d_in[4];
    const float* lin0_b   = (const float*)d_in[5];
    const float* em1_w    = (const float*)d_in[6];
    const float* em1_b    = (const float*)d_in[7];
    const float* em2_w    = (const float*)d_in[8];
    const float* em2_b    = (const float*)d_in[9];
    const float* root_w   = (const float*)d_in[10];
    const float* conv_b   = (const float*)d_in[11];
    const float* gru_wih  = (const float*)d_in[12];
    const float* gru_whh  = (const float*)d_in[13];
    const float* gru_bih  = (const float*)d_in[14];
    const float* gru_bhh  = (const float*)d_in[15];
    const float* lstm_wih = (const float*)d_in[16];
    const float* lstm_whh = (const float*)d_in[17];
    const float* lstm_bih = (const float*)d_in[18];
    const float* lstm_bhh = (const float*)d_in[19];
    const float* lin1_w   = (const float*)d_in[20];
    const float* lin1_b   = (const float*)d_in[21];
    const float* lin3_w   = (const float*)d_in[22];
    const float* lin3_b   = (const float*)d_in[23];

    int n = in_sizes[0] / 3;
    int e = in_sizes[2] / 2;
    if (n > NMAX || e > EMAX) return;

    init_kernel<<<(NMAX + 255) / 256, 256>>>();
    deg_kernel<<<(e + 255) / 256, 256>>>(ei, e);
    lin0_kernel<<<(n * DIM + 255) / 256, 256>>>(x, lin0_w, lin0_b, n);
    edge_mlp1_kernel<<<(e * DIM + 255) / 256, 256>>>(edge_attr, em1_w, em1_b, e);
    em2_convert_kernel<<<(4096 * 64 + 255) / 256, 256>>>(em2_w);
    transpose_gru_kernel<<<(192 * 64 + 255) / 256, 256>>>(gru_wih, gru_whh);

    we_gemm<<<dim3(EMAX / 128, 32), 256>>>(em2_b);

    for (int it = 0; it < 6; it++) {
        zero_agg_kernel<<<(NMAX * DIM + 255) / 256, 256>>>();
        msg_kernel<<<(e * 32 + 255) / 256, 256>>>(ei, e);
        gru_kernel<<<(n + 31) / 32, 256>>>(root_w, conv_b, gru_bih, gru_bhh, n);
    }

    for (int it = 0; it < 6; it++) {
        lstm_kernel<<<1, 256>>>(lstm_wih, lstm_whh, lstm_bih, lstm_bhh, it == 0);
        attn_a_kernel<<<120, 256>>>(n);
        attn_b_kernel<<<120, 256>>>(n);
    }

    final_kernel<<<1, 64>>>(lin1_w, lin1_b, lin3_w, lin3_b, (float*)d_out);
}